// round 1
// baseline (speedup 1.0000x reference)
#include <cuda_runtime.h>
#include <cuda_bf16.h>
#include <math.h>

// ---------------- problem constants ----------------
#define T_TOK   2048
#define D_MODEL 4096
#define N_HEADS 32
#define KV_HEADS 8
#define HEAD_DIM 128
#define GROUPS  4
#define QKV_OUT 6144            // 4096 + 2*8*128
#define CLIP_V  8.0f

// ---------------- scratch (device globals; no allocations) ----------------
__device__ float g_qkv[(size_t)T_TOK * QKV_OUT];   // post-clip, rope applied in place
__device__ float g_attn[(size_t)T_TOK * D_MODEL];  // attention output, (t, h*128+d)

// ===================================================================
// Generic SGEMM:  C[M,N] = A[M,K] @ B[N,K]^T   (both row-major), optional clip
// Block tile 128x128, BK=16, 256 threads, 8x8 per-thread microtile.
// ===================================================================
template <bool CLIP>
__global__ __launch_bounds__(256) void sgemm_nt(const float* __restrict__ A,
                                                const float* __restrict__ B,
                                                float* __restrict__ C,
                                                int N, int K) {
    __shared__ float As[16][128];
    __shared__ float Bs[16][128];

    const int tid = threadIdx.x;
    const int m0 = blockIdx.y * 128;
    const int n0 = blockIdx.x * 128;
    const int ty = tid >> 4;          // 0..15
    const int tx = tid & 15;          // 0..15

    const int lrow  = tid >> 2;       // 0..63
    const int lcol4 = (tid & 3) * 4;  // 0,4,8,12

    const float* Ab = A + (size_t)(m0 + lrow) * K + lcol4;
    const float* Bb = B + (size_t)(n0 + lrow) * K + lcol4;

    float c[8][8];
#pragma unroll
    for (int i = 0; i < 8; i++)
#pragma unroll
        for (int j = 0; j < 8; j++) c[i][j] = 0.f;

    for (int k0 = 0; k0 < K; k0 += 16) {
        float4 a0 = *(const float4*)(Ab + k0);
        float4 a1 = *(const float4*)(Ab + (size_t)64 * K + k0);
        float4 b0 = *(const float4*)(Bb + k0);
        float4 b1 = *(const float4*)(Bb + (size_t)64 * K + k0);
        __syncthreads();
        As[lcol4 + 0][lrow]      = a0.x;
        As[lcol4 + 1][lrow]      = a0.y;
        As[lcol4 + 2][lrow]      = a0.z;
        As[lcol4 + 3][lrow]      = a0.w;
        As[lcol4 + 0][lrow + 64] = a1.x;
        As[lcol4 + 1][lrow + 64] = a1.y;
        As[lcol4 + 2][lrow + 64] = a1.z;
        As[lcol4 + 3][lrow + 64] = a1.w;
        Bs[lcol4 + 0][lrow]      = b0.x;
        Bs[lcol4 + 1][lrow]      = b0.y;
        Bs[lcol4 + 2][lrow]      = b0.z;
        Bs[lcol4 + 3][lrow]      = b0.w;
        Bs[lcol4 + 0][lrow + 64] = b1.x;
        Bs[lcol4 + 1][lrow + 64] = b1.y;
        Bs[lcol4 + 2][lrow + 64] = b1.z;
        Bs[lcol4 + 3][lrow + 64] = b1.w;
        __syncthreads();
#pragma unroll
        for (int k = 0; k < 16; k++) {
            float a[8], b[8];
            *(float4*)(a)     = *(const float4*)&As[k][ty * 8];
            *(float4*)(a + 4) = *(const float4*)&As[k][ty * 8 + 4];
            *(float4*)(b)     = *(const float4*)&Bs[k][tx * 8];
            *(float4*)(b + 4) = *(const float4*)&Bs[k][tx * 8 + 4];
#pragma unroll
            for (int i = 0; i < 8; i++)
#pragma unroll
                for (int j = 0; j < 8; j++) c[i][j] = fmaf(a[i], b[j], c[i][j]);
        }
    }

#pragma unroll
    for (int i = 0; i < 8; i++) {
        float* Crow = C + (size_t)(m0 + ty * 8 + i) * N + n0 + tx * 8;
#pragma unroll
        for (int j4 = 0; j4 < 2; j4++) {
            float4 v;
            v.x = c[i][j4 * 4 + 0];
            v.y = c[i][j4 * 4 + 1];
            v.z = c[i][j4 * 4 + 2];
            v.w = c[i][j4 * 4 + 3];
            if (CLIP) {
                v.x = fminf(fmaxf(v.x, -CLIP_V), CLIP_V);
                v.y = fminf(fmaxf(v.y, -CLIP_V), CLIP_V);
                v.z = fminf(fmaxf(v.z, -CLIP_V), CLIP_V);
                v.w = fminf(fmaxf(v.w, -CLIP_V), CLIP_V);
            }
            ((float4*)Crow)[j4] = v;
        }
    }
}

// ===================================================================
// RoPE in place on q (32 heads) and k (8 heads). v untouched.
// ===================================================================
__global__ void rope_kernel(float* __restrict__ qkv,
                            const float* __restrict__ cosp,
                            const float* __restrict__ sinp) {
    int idx = blockIdx.x * blockDim.x + threadIdx.x;
    const int total = T_TOK * 40 * 64;   // (32 q heads + 8 k heads) * half-dim
    if (idx >= total) return;
    int d  = idx & 63;
    int r  = idx >> 6;
    int hh = r % 40;
    int t  = r / 40;
    size_t base = (size_t)t * QKV_OUT + (hh < 32 ? hh * 128 : 4096 + (hh - 32) * 128);
    float x1 = qkv[base + d];
    float x2 = qkv[base + 64 + d];
    float c = cosp[t * 64 + d];
    float s = sinp[t * 64 + d];
    qkv[base + d]      = x1 * c - x2 * s;
    qkv[base + 64 + d] = x2 * c + x1 * s;
}

// ===================================================================
// Flash-style varlen causal attention, fp32.
// grid = (qtile 0..31, head 0..31), 128 threads.
// Q tile 64 rows, K/V tiles 32 rows. Online softmax.
// smem: Qs 64x132 | Kt 128x33 | Vs 32x128 | Ss 64x33  (75,520 B)
// ===================================================================
#define ATTN_SMEM_FLOATS (64 * 132 + 128 * 33 + 32 * 128 + 64 * 33)
#define ATTN_SMEM_BYTES  (ATTN_SMEM_FLOATS * 4)

__global__ __launch_bounds__(128) void attn_kernel(const float* __restrict__ qkv,
                                                   const int* __restrict__ cu,
                                                   float* __restrict__ attno) {
    extern __shared__ float sm[];
    float* Qs = sm;                       // [64][132]
    float* Kt = Qs + 64 * 132;            // [128][33]  (K transposed: Kt[d][j])
    float* Vs = Kt + 128 * 33;            // [32][128]
    float* Ss = Vs + 32 * 128;            // [64][33]

    const int tid = threadIdx.x;
    const int qt = blockIdx.x;
    const int h  = blockIdx.y;
    const int q0 = qt * 64;
    const int kh = h >> 2;                // GQA: 4 q heads share one kv head

    int seg_start = 0;
#pragma unroll
    for (int s = 1; s < 4; s++) {
        int c = cu[s];
        if (q0 >= c) seg_start = c;
    }

    // load Q tile
    for (int idx = tid; idx < 64 * 128; idx += 128) {
        int i = idx >> 7, d = idx & 127;
        Qs[i * 132 + d] = qkv[(size_t)(q0 + i) * QKV_OUT + h * 128 + d];
    }

    float o[64];
#pragma unroll
    for (int x = 0; x < 64; x++) o[x] = 0.f;
    float m = -1e30f, l = 0.f;

    const int i_own = tid >> 1;           // softmax/PV row owner (2 threads/row)
    const int half  = tid & 1;
    const int igrp  = tid >> 3;           // score phase: 4 rows
    const int jgrp  = tid & 7;            // score phase: 4 cols
    const float scale = 0.08838834764831845f;  // 1/sqrt(128)

    for (int kstart = seg_start; kstart < q0 + 64; kstart += 32) {
        __syncthreads();
        // load K (transposed) and V tiles
        for (int idx = tid; idx < 32 * 128; idx += 128) {
            int j = idx >> 7, d = idx & 127;
            size_t base = (size_t)(kstart + j) * QKV_OUT;
            Kt[d * 33 + j]  = qkv[base + 4096 + kh * 128 + d];
            Vs[j * 128 + d] = qkv[base + 5120 + kh * 128 + d];
        }
        __syncthreads();

        // ---- scores: each thread computes a 4x4 block of S[64][32] ----
        float acc[4][4];
#pragma unroll
        for (int a = 0; a < 4; a++)
#pragma unroll
            for (int b = 0; b < 4; b++) acc[a][b] = 0.f;

#pragma unroll 4
        for (int d = 0; d < 128; d++) {
            float kv[4], qv[4];
#pragma unroll
            for (int b = 0; b < 4; b++) kv[b] = Kt[d * 33 + jgrp * 4 + b];
#pragma unroll
            for (int a = 0; a < 4; a++) qv[a] = Qs[(igrp * 4 + a) * 132 + d];
#pragma unroll
            for (int a = 0; a < 4; a++)
#pragma unroll
                for (int b = 0; b < 4; b++) acc[a][b] = fmaf(qv[a], kv[b], acc[a][b]);
        }
#pragma unroll
        for (int a = 0; a < 4; a++)
#pragma unroll
            for (int b = 0; b < 4; b++) {
                int i = igrp * 4 + a;
                int j = jgrp * 4 + b;
                float v = acc[a][b] * scale;
                if (kstart + j > q0 + i) v = -1e30f;   // causal mask
                Ss[i * 33 + j] = v;
            }
        __syncthreads();

        // ---- online softmax (2 threads per row, redundant stats) ----
        float mx = -1e30f;
#pragma unroll
        for (int j = 0; j < 32; j++) mx = fmaxf(mx, Ss[i_own * 33 + j]);
        float mn = fmaxf(m, mx);
        float sum = 0.f;
#pragma unroll
        for (int j = 0; j < 16; j++) {
            int jj = half * 16 + j;
            float p = __expf(Ss[i_own * 33 + jj] - mn);
            Ss[i_own * 33 + jj] = p;
            sum += p;
        }
        sum += __shfl_xor_sync(0xffffffffu, sum, 1);
        float corr = __expf(m - mn);
        l = l * corr + sum;
        m = mn;
#pragma unroll
        for (int x = 0; x < 64; x++) o[x] *= corr;
        __syncwarp();

        // ---- O += P @ V ----
#pragma unroll 4
        for (int j = 0; j < 32; j++) {
            float p = Ss[i_own * 33 + j];
            const float4* vr = (const float4*)&Vs[j * 128 + half * 64];
#pragma unroll
            for (int d4 = 0; d4 < 16; d4++) {
                float4 v = vr[d4];
                o[d4 * 4 + 0] = fmaf(p, v.x, o[d4 * 4 + 0]);
                o[d4 * 4 + 1] = fmaf(p, v.y, o[d4 * 4 + 1]);
                o[d4 * 4 + 2] = fmaf(p, v.z, o[d4 * 4 + 2]);
                o[d4 * 4 + 3] = fmaf(p, v.w, o[d4 * 4 + 3]);
            }
        }
    }

    float inv = 1.f / l;
    float* orow = attno + (size_t)(q0 + i_own) * D_MODEL + h * 128 + half * 64;
#pragma unroll
    for (int d4 = 0; d4 < 16; d4++) {
        float4 v;
        v.x = o[d4 * 4 + 0] * inv;
        v.y = o[d4 * 4 + 1] * inv;
        v.z = o[d4 * 4 + 2] * inv;
        v.w = o[d4 * 4 + 3] * inv;
        ((float4*)orow)[d4] = v;
    }
}

// ===================================================================
// launch
// ===================================================================
extern "C" void kernel_launch(void* const* d_in, const int* in_sizes, int n_in,
                              void* d_out, int out_size) {
    const float* hidden = (const float*)d_in[0];
    const float* w_qkv  = (const float*)d_in[1];
    const float* w_o    = (const float*)d_in[2];
    const float* cosp   = (const float*)d_in[3];
    const float* sinp   = (const float*)d_in[4];
    const int*   cu     = (const int*)d_in[5];
    float* out = (float*)d_out;

    float *qkvp = nullptr, *attp = nullptr;
    cudaGetSymbolAddress((void**)&qkvp, g_qkv);
    cudaGetSymbolAddress((void**)&attp, g_attn);

    cudaFuncSetAttribute(attn_kernel, cudaFuncAttributeMaxDynamicSharedMemorySize,
                         ATTN_SMEM_BYTES);

    // 1) QKV projection + clip
    sgemm_nt<true><<<dim3(QKV_OUT / 128, T_TOK / 128), 256>>>(hidden, w_qkv, qkvp,
                                                              QKV_OUT, D_MODEL);
    // 2) RoPE (in place on q and k)
    {
        int total = T_TOK * 40 * 64;
        rope_kernel<<<(total + 255) / 256, 256>>>(qkvp, cosp, sinp);
    }
    // 3) attention
    attn_kernel<<<dim3(T_TOK / 64, N_HEADS), 128, ATTN_SMEM_BYTES>>>(qkvp, cu, attp);
    // 4) output projection
    sgemm_nt<false><<<dim3(D_MODEL / 128, T_TOK / 128), 256>>>(attp, w_o, out,
                                                               D_MODEL, D_MODEL);
}

// round 4
// speedup vs baseline: 2.2287x; 2.2287x over previous
#include <cuda_runtime.h>
#include <cuda_bf16.h>
#include <math.h>
#include <stdint.h>

// ---------------- problem constants ----------------
#define T_TOK   2048
#define D_MODEL 4096
#define N_HEADS 32
#define KV_HEADS 8
#define HEAD_DIM 128
#define QKV_OUT 6144            // 4096 + 2*8*128
#define CLIP_V  8.0f
#define GK      4096

// ---------------- scratch (device globals; no allocations) ----------------
__device__ float g_qkv[(size_t)T_TOK * QKV_OUT];
__device__ float g_attn[(size_t)T_TOK * D_MODEL];

__device__ __nv_bfloat16 g_hid_h[(size_t)T_TOK * D_MODEL];
__device__ __nv_bfloat16 g_hid_l[(size_t)T_TOK * D_MODEL];
__device__ __nv_bfloat16 g_wqkv_h[(size_t)QKV_OUT * D_MODEL];
__device__ __nv_bfloat16 g_wqkv_l[(size_t)QKV_OUT * D_MODEL];
__device__ __nv_bfloat16 g_wo_h[(size_t)D_MODEL * D_MODEL];
__device__ __nv_bfloat16 g_wo_l[(size_t)D_MODEL * D_MODEL];
__device__ __nv_bfloat16 g_att_h[(size_t)T_TOK * D_MODEL];
__device__ __nv_bfloat16 g_att_l[(size_t)T_TOK * D_MODEL];

// ---------------- helpers ----------------
__device__ __forceinline__ uint32_t smem_u32(const void* p) {
    uint32_t a;
    asm("{ .reg .u64 t; cvta.to.shared.u64 t, %1; cvt.u32.u64 %0, t; }"
        : "=r"(a) : "l"(p));
    return a;
}
__device__ __forceinline__ void ldsm4(uint32_t addr, uint32_t* r) {
    asm volatile("ldmatrix.sync.aligned.m8n8.x4.shared.b16 {%0,%1,%2,%3}, [%4];"
                 : "=r"(r[0]), "=r"(r[1]), "=r"(r[2]), "=r"(r[3]) : "r"(addr));
}
__device__ __forceinline__ void mma_bf16(float* d, const uint32_t* a,
                                         uint32_t b0, uint32_t b1) {
    asm volatile(
        "mma.sync.aligned.m16n8k16.row.col.f32.bf16.bf16.f32 "
        "{%0,%1,%2,%3}, {%4,%5,%6,%7}, {%8,%9}, {%0,%1,%2,%3};"
        : "+f"(d[0]), "+f"(d[1]), "+f"(d[2]), "+f"(d[3])
        : "r"(a[0]), "r"(a[1]), "r"(a[2]), "r"(a[3]), "r"(b0), "r"(b1));
}

// ===================================================================
// Split fp32 -> (hi, lo) bf16
// ===================================================================
__global__ __launch_bounds__(256) void split_bf16(const float* __restrict__ x,
                                                  __nv_bfloat16* __restrict__ hi,
                                                  __nv_bfloat16* __restrict__ lo,
                                                  int n4) {
    int i = blockIdx.x * blockDim.x + threadIdx.x;
    if (i >= n4) return;
    float4 f = ((const float4*)x)[i];
    __nv_bfloat16 h[4], l[4];
    float v[4] = {f.x, f.y, f.z, f.w};
#pragma unroll
    for (int j = 0; j < 4; j++) {
        h[j] = __float2bfloat16_rn(v[j]);
        l[j] = __float2bfloat16_rn(v[j] - __bfloat162float(h[j]));
    }
    ((uint2*)hi)[i] = *(uint2*)h;
    ((uint2*)lo)[i] = *(uint2*)l;
}

// ===================================================================
// bf16 split-precision GEMM via mma.sync:
//   C[M,N] = A[M,K] @ B[N,K]^T,  K = 4096
// CTA 128x128, BK=32, 256 thr (8 warps, 2x4), warp tile 64x32.
// D = Ah*Bh + Ah*Bl + Al*Bh, fp32 register accumulators.
// smem rows padded to 40 bf16 (80B) -> conflict-free ldmatrix.
// ===================================================================
#define PADK       40
#define TILE_BY    (128 * PADK * 2)        // 10240 B per matrix tile
#define STAGE_BY   (4 * TILE_BY)           // Ah|Al|Bh|Bl = 40960 B
#define GEMM_SMEM  (2 * STAGE_BY)          // 81920 B
#define KT_N       (GK / 32)               // 128

template <bool CLIP>
__global__ __launch_bounds__(256) void gemm_mma_split(
    const __nv_bfloat16* __restrict__ Ah, const __nv_bfloat16* __restrict__ Al,
    const __nv_bfloat16* __restrict__ Bh, const __nv_bfloat16* __restrict__ Bl,
    float* __restrict__ C, int N) {
    extern __shared__ char dsm[];
    const uint32_t sb = smem_u32(dsm);

    const int tid = threadIdx.x;
    const int wid = tid >> 5, lane = tid & 31;
    const int warp_m = wid & 1, warp_n = wid >> 1;
    const int m0 = blockIdx.y * 128, n0 = blockIdx.x * 128;

    const __nv_bfloat16* gsrc[4] = {
        Ah + (size_t)m0 * GK, Al + (size_t)m0 * GK,
        Bh + (size_t)n0 * GK, Bl + (size_t)n0 * GK};

    // ldmatrix per-lane byte offsets (within a stage)
    const int g = lane >> 3, r = lane & 7;
    uint32_t a_off[4], b_off[2];
#pragma unroll
    for (int fm = 0; fm < 4; fm++)
        a_off[fm] = (uint32_t)((warp_m * 64 + fm * 16 + (g & 1) * 8 + r) * (PADK * 2)
                               + (g >> 1) * 16);
#pragma unroll
    for (int nf = 0; nf < 2; nf++)
        b_off[nf] = (uint32_t)((warp_n * 32 + nf * 16 + (g >> 1) * 8 + r) * (PADK * 2)
                               + (g & 1) * 16);

    float acc[4][4][4];
#pragma unroll
    for (int i = 0; i < 4; i++)
#pragma unroll
        for (int j = 0; j < 4; j++)
#pragma unroll
            for (int q = 0; q < 4; q++) acc[i][j][q] = 0.f;

    // cp.async prefetch of one BK=32 stage
    auto prefetch = [&](int kt) {
        const uint32_t so = sb + (uint32_t)(kt & 1) * STAGE_BY;
        const int k0 = kt * 32;
#pragma unroll
        for (int it = 0; it < 8; it++) {
            int gi = tid + it * 256;
            int tile = gi >> 9;
            int w = gi & 511;
            int row = w >> 2, c = w & 3;
            const char* src = (const char*)(gsrc[tile] + (size_t)row * GK + k0 + c * 8);
            uint32_t dst = so + (uint32_t)(tile * TILE_BY + row * (PADK * 2) + c * 16);
            asm volatile("cp.async.cg.shared.global [%0], [%1], 16;"
                         :: "r"(dst), "l"(src));
        }
        asm volatile("cp.async.commit_group;");
    };

    prefetch(0);

    for (int kt = 0; kt < KT_N; kt++) {
        if (kt + 1 < KT_N) {
            prefetch(kt + 1);
            asm volatile("cp.async.wait_group 1;");
        } else {
            asm volatile("cp.async.wait_group 0;");
        }
        __syncthreads();

        const uint32_t so = sb + (uint32_t)(kt & 1) * STAGE_BY;
#pragma unroll
        for (int ks = 0; ks < 2; ks++) {
            const uint32_t ko = (uint32_t)(ks * 32);
            uint32_t Af[4][4], Lf[4][4], Bf[2][4], Mf[2][4];
#pragma unroll
            for (int fm = 0; fm < 4; fm++) {
                ldsm4(so + a_off[fm] + ko, Af[fm]);
                ldsm4(so + TILE_BY + a_off[fm] + ko, Lf[fm]);
            }
#pragma unroll
            for (int nf = 0; nf < 2; nf++) {
                ldsm4(so + 2 * TILE_BY + b_off[nf] + ko, Bf[nf]);
                ldsm4(so + 3 * TILE_BY + b_off[nf] + ko, Mf[nf]);
            }
#pragma unroll
            for (int fm = 0; fm < 4; fm++)
#pragma unroll
                for (int fn = 0; fn < 4; fn++) {
                    const int n2 = fn >> 1, j = (fn & 1) * 2;
                    mma_bf16(acc[fm][fn], Af[fm], Bf[n2][j], Bf[n2][j + 1]);
                    mma_bf16(acc[fm][fn], Af[fm], Mf[n2][j], Mf[n2][j + 1]);
                    mma_bf16(acc[fm][fn], Lf[fm], Bf[n2][j], Bf[n2][j + 1]);
                }
        }
        __syncthreads();
    }

    // epilogue: direct fp32 stores (float2 per fragment row)
    const int mrow = m0 + warp_m * 64 + (lane >> 2);
    const int ncol = n0 + warp_n * 32 + (lane & 3) * 2;
#pragma unroll
    for (int fm = 0; fm < 4; fm++)
#pragma unroll
        for (int fn = 0; fn < 4; fn++) {
            float* p0 = C + (size_t)(mrow + fm * 16) * N + ncol + fn * 8;
            float* p1 = p0 + (size_t)8 * N;
            float2 v0 = {acc[fm][fn][0], acc[fm][fn][1]};
            float2 v1 = {acc[fm][fn][2], acc[fm][fn][3]};
            if (CLIP) {
                v0.x = fminf(fmaxf(v0.x, -CLIP_V), CLIP_V);
                v0.y = fminf(fmaxf(v0.y, -CLIP_V), CLIP_V);
                v1.x = fminf(fmaxf(v1.x, -CLIP_V), CLIP_V);
                v1.y = fminf(fmaxf(v1.y, -CLIP_V), CLIP_V);
            }
            *(float2*)p0 = v0;
            *(float2*)p1 = v1;
        }
}

// ===================================================================
// RoPE in place on q (32 heads) and k (8 heads).
// ===================================================================
__global__ void rope_kernel(float* __restrict__ qkv,
                            const float* __restrict__ cosp,
                            const float* __restrict__ sinp) {
    int idx = blockIdx.x * blockDim.x + threadIdx.x;
    const int total = T_TOK * 40 * 64;
    if (idx >= total) return;
    int d  = idx & 63;
    int r  = idx >> 6;
    int hh = r % 40;
    int t  = r / 40;
    size_t base = (size_t)t * QKV_OUT + (hh < 32 ? hh * 128 : 4096 + (hh - 32) * 128);
    float x1 = qkv[base + d];
    float x2 = qkv[base + 64 + d];
    float c = cosp[t * 64 + d];
    float s = sinp[t * 64 + d];
    qkv[base + d]      = x1 * c - x2 * s;
    qkv[base + 64 + d] = x2 * c + x1 * s;
}

// ===================================================================
// Flash-style varlen causal attention, fp32 (unchanged — proven).
// ===================================================================
#define ATTN_SMEM_FLOATS (64 * 132 + 128 * 33 + 32 * 128 + 64 * 33)
#define ATTN_SMEM_BYTES  (ATTN_SMEM_FLOATS * 4)

__global__ __launch_bounds__(128) void attn_kernel(const float* __restrict__ qkv,
                                                   const int* __restrict__ cu,
                                                   float* __restrict__ attno) {
    extern __shared__ float sm[];
    float* Qs = sm;
    float* Kt = Qs + 64 * 132;
    float* Vs = Kt + 128 * 33;
    float* Ss = Vs + 32 * 128;

    const int tid = threadIdx.x;
    const int qt = blockIdx.x;
    const int h  = blockIdx.y;
    const int q0 = qt * 64;
    const int kh = h >> 2;

    int seg_start = 0;
#pragma unroll
    for (int s = 1; s < 4; s++) {
        int c = cu[s];
        if (q0 >= c) seg_start = c;
    }

    for (int idx = tid; idx < 64 * 128; idx += 128) {
        int i = idx >> 7, d = idx & 127;
        Qs[i * 132 + d] = qkv[(size_t)(q0 + i) * QKV_OUT + h * 128 + d];
    }

    float o[64];
#pragma unroll
    for (int x = 0; x < 64; x++) o[x] = 0.f;
    float m = -1e30f, l = 0.f;

    const int i_own = tid >> 1;
    const int half  = tid & 1;
    const int igrp  = tid >> 3;
    const int jgrp  = tid & 7;
    const float scale = 0.08838834764831845f;

    for (int kstart = seg_start; kstart < q0 + 64; kstart += 32) {
        __syncthreads();
        for (int idx = tid; idx < 32 * 128; idx += 128) {
            int j = idx >> 7, d = idx & 127;
            size_t base = (size_t)(kstart + j) * QKV_OUT;
            Kt[d * 33 + j]  = qkv[base + 4096 + kh * 128 + d];
            Vs[j * 128 + d] = qkv[base + 5120 + kh * 128 + d];
        }
        __syncthreads();

        float acc[4][4];
#pragma unroll
        for (int a = 0; a < 4; a++)
#pragma unroll
            for (int b = 0; b < 4; b++) acc[a][b] = 0.f;

#pragma unroll 4
        for (int d = 0; d < 128; d++) {
            float kv[4], qv[4];
#pragma unroll
            for (int b = 0; b < 4; b++) kv[b] = Kt[d * 33 + jgrp * 4 + b];
#pragma unroll
            for (int a = 0; a < 4; a++) qv[a] = Qs[(igrp * 4 + a) * 132 + d];
#pragma unroll
            for (int a = 0; a < 4; a++)
#pragma unroll
                for (int b = 0; b < 4; b++) acc[a][b] = fmaf(qv[a], kv[b], acc[a][b]);
        }
#pragma unroll
        for (int a = 0; a < 4; a++)
#pragma unroll
            for (int b = 0; b < 4; b++) {
                int i = igrp * 4 + a;
                int j = jgrp * 4 + b;
                float v = acc[a][b] * scale;
                if (kstart + j > q0 + i) v = -1e30f;
                Ss[i * 33 + j] = v;
            }
        __syncthreads();

        float mx = -1e30f;
#pragma unroll
        for (int j = 0; j < 32; j++) mx = fmaxf(mx, Ss[i_own * 33 + j]);
        float mn = fmaxf(m, mx);
        float sum = 0.f;
#pragma unroll
        for (int j = 0; j < 16; j++) {
            int jj = half * 16 + j;
            float p = __expf(Ss[i_own * 33 + jj] - mn);
            Ss[i_own * 33 + jj] = p;
            sum += p;
        }
        sum += __shfl_xor_sync(0xffffffffu, sum, 1);
        float corr = __expf(m - mn);
        l = l * corr + sum;
        m = mn;
#pragma unroll
        for (int x = 0; x < 64; x++) o[x] *= corr;
        __syncwarp();

#pragma unroll 4
        for (int j = 0; j < 32; j++) {
            float p = Ss[i_own * 33 + j];
            const float4* vr = (const float4*)&Vs[j * 128 + half * 64];
#pragma unroll
            for (int d4 = 0; d4 < 16; d4++) {
                float4 v = vr[d4];
                o[d4 * 4 + 0] = fmaf(p, v.x, o[d4 * 4 + 0]);
                o[d4 * 4 + 1] = fmaf(p, v.y, o[d4 * 4 + 1]);
                o[d4 * 4 + 2] = fmaf(p, v.z, o[d4 * 4 + 2]);
                o[d4 * 4 + 3] = fmaf(p, v.w, o[d4 * 4 + 3]);
            }
        }
    }

    float inv = 1.f / l;
    float* orow = attno + (size_t)(q0 + i_own) * D_MODEL + h * 128 + half * 64;
#pragma unroll
    for (int d4 = 0; d4 < 16; d4++) {
        float4 v;
        v.x = o[d4 * 4 + 0] * inv;
        v.y = o[d4 * 4 + 1] * inv;
        v.z = o[d4 * 4 + 2] * inv;
        v.w = o[d4 * 4 + 3] * inv;
        ((float4*)orow)[d4] = v;
    }
}

// ===================================================================
// launch
// ===================================================================
extern "C" void kernel_launch(void* const* d_in, const int* in_sizes, int n_in,
                              void* d_out, int out_size) {
    const float* hidden = (const float*)d_in[0];
    const float* w_qkv  = (const float*)d_in[1];
    const float* w_o    = (const float*)d_in[2];
    const float* cosp   = (const float*)d_in[3];
    const float* sinp   = (const float*)d_in[4];
    const int*   cu     = (const int*)d_in[5];
    float* out = (float*)d_out;

    float *qkvp = nullptr, *attp = nullptr;
    __nv_bfloat16 *hh, *hl, *wqh, *wql, *woh, *wol, *ath, *atl;
    cudaGetSymbolAddress((void**)&qkvp, g_qkv);
    cudaGetSymbolAddress((void**)&attp, g_attn);
    cudaGetSymbolAddress((void**)&hh,  g_hid_h);
    cudaGetSymbolAddress((void**)&hl,  g_hid_l);
    cudaGetSymbolAddress((void**)&wqh, g_wqkv_h);
    cudaGetSymbolAddress((void**)&wql, g_wqkv_l);
    cudaGetSymbolAddress((void**)&woh, g_wo_h);
    cudaGetSymbolAddress((void**)&wol, g_wo_l);
    cudaGetSymbolAddress((void**)&ath, g_att_h);
    cudaGetSymbolAddress((void**)&atl, g_att_l);

    cudaFuncSetAttribute(attn_kernel, cudaFuncAttributeMaxDynamicSharedMemorySize,
                         ATTN_SMEM_BYTES);
    cudaFuncSetAttribute(gemm_mma_split<true>,
                         cudaFuncAttributeMaxDynamicSharedMemorySize, GEMM_SMEM);
    cudaFuncSetAttribute(gemm_mma_split<false>,
                         cudaFuncAttributeMaxDynamicSharedMemorySize, GEMM_SMEM);

    // 0) split inputs/weights into bf16 hi/lo
    {
        int n4;
        n4 = T_TOK * D_MODEL / 4;
        split_bf16<<<(n4 + 255) / 256, 256>>>(hidden, hh, hl, n4);
        n4 = QKV_OUT * D_MODEL / 4;
        split_bf16<<<(n4 + 255) / 256, 256>>>(w_qkv, wqh, wql, n4);
        n4 = D_MODEL * D_MODEL / 4;
        split_bf16<<<(n4 + 255) / 256, 256>>>(w_o, woh, wol, n4);
    }
    // 1) QKV projection + clip (tensor cores, mma.sync)
    gemm_mma_split<true><<<dim3(QKV_OUT / 128, T_TOK / 128), 256, GEMM_SMEM>>>(
        hh, hl, wqh, wql, qkvp, QKV_OUT);
    // 2) RoPE
    {
        int total = T_TOK * 40 * 64;
        rope_kernel<<<(total + 255) / 256, 256>>>(qkvp, cosp, sinp);
    }
    // 3) attention (fp32)
    attn_kernel<<<dim3(T_TOK / 64, N_HEADS), 128, ATTN_SMEM_BYTES>>>(qkvp, cu, attp);
    // 4) split attention output, then output projection
    {
        int n4 = T_TOK * D_MODEL / 4;
        split_bf16<<<(n4 + 255) / 256, 256>>>(attp, ath, atl, n4);
    }
    gemm_mma_split<false><<<dim3(D_MODEL / 128, T_TOK / 128), 256, GEMM_SMEM>>>(
        ath, atl, woh, wol, out, D_MODEL);
}